// round 5
// baseline (speedup 1.0000x reference)
#include <cuda_runtime.h>

#define BB 2
#define NN 1024
#define DD 3
#define F1 32
#define F2 64
#define NTH 512
#define NB 256          // histogram bins

// Scratch (no allocs allowed). Transposed layouts: [batch][feature][point]
__device__ float g_h1[BB*F1*NN];
__device__ float g_h2[BB*F2*NN];
__device__ float g_Hsum[BB*F2];

// ---------------------------------------------------------------------------
// Rank-query engine: given per-thread c values (c0 at index t, c1 at t+512)
// and queries q = -a, computes for each query:
//   cnt = #{c_j > q},  sum = sum{c_j > q}
// via 256-bin counting histogram + bucket scan. Ties are harmless because
// their contribution a + c == 0.
// Shared arrays are passed in; all threads must call (uniform barriers).
// ---------------------------------------------------------------------------
struct RankSmem {
    int   cnt[NB];
    int   cur[NB];
    float bsum[NB];
    int   E[NB+1];
    float SS[NB+1];
    float sc[NN];
    float redA[16];
    float redB[16];
};

__device__ __forceinline__ void rank_build(RankSmem* S, float c0, float c1,
                                           int t, float& mn_out, float& invw_out)
{
    int lane = t & 31, w = t >> 5;

    // zero histogram
    if (t < NB) { S->cnt[t] = 0; S->bsum[t] = 0.0f; }

    // block min/max of c
    float mnl = fminf(c0, c1), mxl = fmaxf(c0, c1);
#pragma unroll
    for (int o = 16; o > 0; o >>= 1) {
        mnl = fminf(mnl, __shfl_xor_sync(0xffffffffu, mnl, o));
        mxl = fmaxf(mxl, __shfl_xor_sync(0xffffffffu, mxl, o));
    }
    if (lane == 0) { S->redA[w] = mnl; S->redB[w] = mxl; }
    __syncthreads();
    if (t < 16) {
        mnl = S->redA[t]; mxl = S->redB[t];
#pragma unroll
        for (int o = 8; o > 0; o >>= 1) {
            mnl = fminf(mnl, __shfl_xor_sync(0x0000ffffu, mnl, o));
            mxl = fmaxf(mxl, __shfl_xor_sync(0x0000ffffu, mxl, o));
        }
        if (t == 0) { S->redA[0] = mnl; S->redB[0] = (float)NB / fmaxf(mxl - mnl, 1e-30f); }
    }
    __syncthreads();
    float mn = S->redA[0], invw = S->redB[0];
    mn_out = mn; invw_out = invw;

    // histogram (counts + sums)
    int b0 = min(max((int)((c0 - mn) * invw), 0), NB-1);
    int b1 = min(max((int)((c1 - mn) * invw), 0), NB-1);
    atomicAdd(&S->cnt[b0], 1);  atomicAdd(&S->bsum[b0], c0);
    atomicAdd(&S->cnt[b1], 1);  atomicAdd(&S->bsum[b1], c1);
    __syncthreads();

    // exclusive scan over NB bins (count + sum), 8 warps
    int v = 0; float s = 0.0f;
    int vi = 0; float si = 0.0f;
    if (t < NB) {
        v = S->cnt[t]; s = S->bsum[t];
        vi = v; si = s;
#pragma unroll
        for (int o = 1; o < 32; o <<= 1) {
            int   nv = __shfl_up_sync(0xffffffffu, vi, o);
            float ns = __shfl_up_sync(0xffffffffu, si, o);
            if (lane >= o) { vi += nv; si += ns; }
        }
        if (lane == 31) { S->redA[w] = (float)vi; S->redB[w] = si; }
    }
    __syncthreads();
    if (t < 8) {
        float v8 = S->redA[t], s8 = S->redB[t];
        float vv = v8, ss = s8;
#pragma unroll
        for (int o = 1; o < 8; o <<= 1) {
            float nv = __shfl_up_sync(0x000000ffu, vv, o);
            float ns = __shfl_up_sync(0x000000ffu, ss, o);
            if (t >= o) { vv += nv; ss += ns; }
        }
        S->redA[t] = vv - v8;   // exclusive warp offsets
        S->redB[t] = ss - s8;
    }
    __syncthreads();
    if (t < NB) {
        int   excl  = vi - v + (int)S->redA[w];
        float exclS = si - s + S->redB[w];
        S->E[t] = excl; S->SS[t] = exclS; S->cur[t] = excl;
        if (t == NB-1) { S->E[NB] = excl + v; S->SS[NB] = exclS + s; }
    }
    __syncthreads();

    // counting-sort scatter of c into bucket-ordered array
    int p0 = atomicAdd(&S->cur[b0], 1);  S->sc[p0] = c0;
    int p1 = atomicAdd(&S->cur[b1], 1);  S->sc[p1] = c1;
    __syncthreads();
}

__device__ __forceinline__ float rank_query(const RankSmem* S, float a, float cself,
                                            float mn, float invw)
{
    const float scale = 1.0f / (float)(NN - 1);
    float q = -a;
    int qb = min(max((int)((q - mn) * invw), 0), NB-1);
    int beg = S->E[qb], end = S->E[qb+1];
    float cnt = (float)(NN - end);
    float sum = S->SS[NB] - S->SS[qb+1];
    for (int k = beg; k < end; k++) {
        float v = S->sc[k];
        if (v > q) { cnt += 1.0f; sum += v; }
    }
    float self = fmaxf(a + cself, 0.0f);
    return (a * cnt + sum - self) * scale;
}

// ---------------------------------------------------------------------------
// Stage 1: one block per (batch, feature f of 32).
//   a_i = x_i . W1top[:,f] + b1[f];  c_j = x_j . W1bot[:,f]
// ---------------------------------------------------------------------------
__global__ __launch_bounds__(NTH) void stage1(
    const float* __restrict__ x,
    const float* __restrict__ W1,
    const float* __restrict__ b1)
{
    __shared__ RankSmem S;

    int t = threadIdx.x;
    int b = blockIdx.x >> 5;
    int f = blockIdx.x & 31;

    float w0 = W1[0*F1+f], w1 = W1[1*F1+f], w2 = W1[2*F1+f];
    float w3 = W1[3*F1+f], w4 = W1[4*F1+f], w5 = W1[5*F1+f];
    float bias = b1[f];
    const float* xb = x + b*NN*DD;

    float a0, a1, c0, c1;
    {
        float x0 = xb[3*t+0], x1 = xb[3*t+1], x2 = xb[3*t+2];
        a0 = x0*w0 + x1*w1 + x2*w2 + bias;
        c0 = x0*w3 + x1*w4 + x2*w5;
        int p = t + 512;
        x0 = xb[3*p+0]; x1 = xb[3*p+1]; x2 = xb[3*p+2];
        a1 = x0*w0 + x1*w1 + x2*w2 + bias;
        c1 = x0*w3 + x1*w4 + x2*w5;
    }

    float mn, invw;
    rank_build(&S, c0, c1, t, mn, invw);

    float* hout = g_h1 + (b*F1 + f)*NN;
    hout[t]       = rank_query(&S, a0, c0, mn, invw);
    hout[t + 512] = rank_query(&S, a1, c1, mn, invw);
}

// ---------------------------------------------------------------------------
// Stage 2: one block per (batch, feature f2 of 64). Also writes Hsum[b][f2].
// ---------------------------------------------------------------------------
__global__ __launch_bounds__(NTH) void stage2(
    const float* __restrict__ W2,
    const float* __restrict__ b2)
{
    __shared__ RankSmem S;
    __shared__ float wt[F1], wb[F1];

    int t = threadIdx.x;
    int b = blockIdx.x >> 6;
    int f2 = blockIdx.x & 63;

    if (t < F1) {
        wt[t] = W2[t*F2 + f2];
        wb[t] = W2[(F1 + t)*F2 + f2];
    }
    float bias = b2[t < 1 ? f2 : f2];  // uniform load
    bias = b2[f2];
    __syncthreads();

    const float* h1b = g_h1 + b*F1*NN;
    float a0 = bias, c0 = 0.0f, a1 = bias, c1 = 0.0f;
#pragma unroll
    for (int f = 0; f < F1; f++) {
        float hv0 = __ldg(&h1b[f*NN + t]);
        float hv1 = __ldg(&h1b[f*NN + t + 512]);
        a0 += hv0 * wt[f];  c0 += hv0 * wb[f];
        a1 += hv1 * wt[f];  c1 += hv1 * wb[f];
    }

    float mn, invw;
    rank_build(&S, c0, c1, t, mn, invw);

    float* hout = g_h2 + (b*F2 + f2)*NN;
    float h0 = rank_query(&S, a0, c0, mn, invw);
    float h1 = rank_query(&S, a1, c1, mn, invw);
    hout[t]       = h0;
    hout[t + 512] = h1;

    // block-reduce (h0 + h1) -> Hsum[b][f2]
    float hloc = h0 + h1;
    __syncthreads();
    int lane = t & 31, w = t >> 5;
#pragma unroll
    for (int o = 16; o > 0; o >>= 1)
        hloc += __shfl_xor_sync(0xffffffffu, hloc, o);
    if (lane == 0) S.redA[w] = hloc;
    __syncthreads();
    if (t < 16) {
        float v = S.redA[t];
#pragma unroll
        for (int o = 8; o > 0; o >>= 1)
            v += __shfl_xor_sync(0x0000ffffu, v, o);
        if (t == 0) g_Hsum[b*F2 + f2] = v;
    }
}

// ---------------------------------------------------------------------------
// Final: block 3 has no relu -> fully closed form, fused projection.
//   out_i = (h2_i @ W3top + b3) + ((Hsum_b - h2_i) @ W3bot) / (N-1)
// ---------------------------------------------------------------------------
__global__ __launch_bounds__(256) void final_k(
    float* __restrict__ out,
    const float* __restrict__ W3,
    const float* __restrict__ b3)
{
    __shared__ float w3s[2*F2*DD];   // 384 floats
    __shared__ float Ssh[DD];

    int tid = threadIdx.x;
    int pg = blockIdx.x * 256 + tid;
    int b = pg >> 10;
    int pi = pg & (NN - 1);

    for (int k = tid; k < 2*F2*DD; k += 256) w3s[k] = W3[k];
    __syncthreads();
    if (tid < DD) {
        float acc = 0.0f;
        const float* Hs = g_Hsum + b*F2;
#pragma unroll
        for (int f = 0; f < F2; f++) acc += Hs[f] * w3s[(F2+f)*DD + tid];
        Ssh[tid] = acc;
    }
    __syncthreads();

    float a0 = b3[0], a1 = b3[1], a2 = b3[2];
    float c0 = 0.0f, c1 = 0.0f, c2 = 0.0f;
    const float* h2b = g_h2 + b*F2*NN;
#pragma unroll
    for (int f = 0; f < F2; f++) {
        float hv = h2b[f*NN + pi];
        a0 += hv * w3s[f*DD+0];
        a1 += hv * w3s[f*DD+1];
        a2 += hv * w3s[f*DD+2];
        c0 += hv * w3s[(F2+f)*DD+0];
        c1 += hv * w3s[(F2+f)*DD+1];
        c2 += hv * w3s[(F2+f)*DD+2];
    }
    const float scale = 1.0f / (float)(NN - 1);
    out[pg*3+0] = a0 + (Ssh[0] - c0) * scale;
    out[pg*3+1] = a1 + (Ssh[1] - c1) * scale;
    out[pg*3+2] = a2 + (Ssh[2] - c2) * scale;
}

// ---------------------------------------------------------------------------
extern "C" void kernel_launch(void* const* d_in, const int* in_sizes, int n_in,
                              void* d_out, int out_size)
{
    const float* x  = (const float*)d_in[0];   // (2, 3072)
    const float* W1 = (const float*)d_in[1];   // (6, 32)
    const float* b1 = (const float*)d_in[2];   // (32,)
    const float* W2 = (const float*)d_in[3];   // (64, 64)
    const float* b2 = (const float*)d_in[4];   // (64,)
    const float* W3 = (const float*)d_in[5];   // (128, 3)
    const float* b3 = (const float*)d_in[6];   // (3,)
    float* out = (float*)d_out;

    stage1<<<BB*F1, NTH>>>(x, W1, b1);         // 64 blocks
    stage2<<<BB*F2, NTH>>>(W2, b2);            // 128 blocks
    final_k<<<BB*NN/256, 256>>>(out, W3, b3);  // 8 blocks
}